// round 6
// baseline (speedup 1.0000x reference)
#include <cuda_runtime.h>
#include <cuda_bf16.h>
#include <math.h>
#include <stdint.h>
#include <stddef.h>

#define N_SPECIES   4
#define NFEAT       7584
#define HID         256
#define ATOMS_PER_S 8192
#define N_ATOMS_C   32768
#define N_STRUCT_C  1024

// ---------------- scratch (__device__ globals; no allocations) ----------------
__device__ uint32_t g_w1h[N_SPECIES * (NFEAT / 2) * HID];
__device__ uint32_t g_w1l[N_SPECIES * (NFEAT / 2) * HID];
__device__ uint32_t g_w2h[N_SPECIES * (HID / 2) * HID];
__device__ uint32_t g_w2l[N_SPECIES * (HID / 2) * HID];
__device__ uint32_t g_w3h[N_SPECIES * (HID / 2) * HID];
__device__ uint32_t g_w3l[N_SPECIES * (HID / 2) * HID];
__device__ float    g_h1[(size_t)N_ATOMS_C * HID];
__device__ float    g_h2[(size_t)N_ATOMS_C * HID];
__device__ float    g_e[N_ATOMS_C];

// ---------------- helpers -----------------------------------------------------
static __device__ __forceinline__ uint32_t pack_bf16(__nv_bfloat16 a, __nv_bfloat16 b) {
    return (uint32_t)__bfloat16_as_ushort(a) | ((uint32_t)__bfloat16_as_ushort(b) << 16);
}

// Split (x0,x1) into hi bf16 pair and lo (residual) bf16 pair, packed .b32 (low = x0).
static __device__ __forceinline__ void split_pack(float x0, float x1,
                                                  uint32_t& h, uint32_t& l) {
    __nv_bfloat16 h0 = __float2bfloat16(x0);
    __nv_bfloat16 h1 = __float2bfloat16(x1);
    float r0 = x0 - __bfloat162float(h0);
    float r1 = x1 - __bfloat162float(h1);
    h = pack_bf16(h0, h1);
    l = pack_bf16(__float2bfloat16(r0), __float2bfloat16(r1));
}

static __device__ __forceinline__ void mma16816(float* d,
                                                uint32_t a0, uint32_t a1, uint32_t a2, uint32_t a3,
                                                uint32_t b0, uint32_t b1) {
    asm volatile(
        "mma.sync.aligned.m16n8k16.row.col.f32.bf16.bf16.f32 "
        "{%0,%1,%2,%3}, {%4,%5,%6,%7}, {%8,%9}, {%0,%1,%2,%3};\n"
        : "+f"(d[0]), "+f"(d[1]), "+f"(d[2]), "+f"(d[3])
        : "r"(a0), "r"(a1), "r"(a2), "r"(a3), "r"(b0), "r"(b1));
}

static __device__ __forceinline__ float silu_f(float x) {
    return x / (1.0f + expf(-x));
}

// ---------------- weight pre-split: fp32 [S][K][256] -> packed k-pair hi/lo ----
// Word p packs (W[2*k2][n], W[2*k2+1][n]); rp = p>>8 = s*(K/2)+k2, n = p&255.
template <int LAYER>
__global__ void conv_w(const float* __restrict__ W, int npairs) {
    uint32_t* Wh = (LAYER == 0) ? g_w1h : (LAYER == 1) ? g_w2h : g_w3h;
    uint32_t* Wl = (LAYER == 0) ? g_w1l : (LAYER == 1) ? g_w2l : g_w3l;
    int p = blockIdx.x * blockDim.x + threadIdx.x;
    if (p >= npairs) return;
    int n = p & (HID - 1);
    size_t rp = (size_t)(p >> 8);
    size_t src = rp * (2 * HID) + n;
    uint32_t h, l;
    split_pack(W[src], W[src + HID], h, l);
    Wh[p] = h;
    Wl[p] = l;
}

// ---------------- fused grouped GEMM + bias + SiLU ----------------------------
// out[s*8192+m, n] = silu( A[s*8192+m, :] dot W[s][:, n] + bias[s][n] )
// BM=128, BN=128, BK=32; 256 threads = 8 warps (2x4), warp tile 64x32.
// Split-bf16: acc += Ah*Bh + Al*Bh + Ah*Bl.
template <int LAYER>
__global__ __launch_bounds__(256, 2) void gemm_silu(
    const float* __restrict__ feat, const float* __restrict__ bias) {

    constexpr int K = (LAYER == 0) ? NFEAT : HID;
    constexpr int ksteps = K >> 5;

    const float* A = (LAYER == 0) ? feat : (LAYER == 1) ? g_h1 : g_h2;
    const uint32_t* Wh = (LAYER == 0) ? g_w1h : (LAYER == 1) ? g_w2h : g_w3h;
    const uint32_t* Wl = (LAYER == 0) ? g_w1l : (LAYER == 1) ? g_w2l : g_w3l;
    float* out = (LAYER == 0) ? g_h1 : (LAYER == 1) ? g_h2 : g_h1;

    // Padded, bank-conflict-free layouts.
    __shared__ __align__(16) uint32_t sAh[128 * 20];   // [row][k2 word], 16 used + 4 pad
    __shared__ __align__(16) uint32_t sAl[128 * 20];
    __shared__ __align__(16) uint32_t sBh[16 * 136];   // [k2][n], 128 used + 8 pad
    __shared__ __align__(16) uint32_t sBl[16 * 136];

    const int tid  = threadIdx.x;
    const int lane = tid & 31;
    const int warp = tid >> 5;
    const int r = lane >> 2;      // groupID (0..7)
    const int c = lane & 3;       // threadID_in_group (0..3)
    const int wm = warp >> 2;     // 0..1
    const int wn = warp & 3;      // 0..3
    const int mt = blockIdx.x;    // 0..63
    const int nt = blockIdx.y;    // 0..1
    const int sp = blockIdx.z;    // 0..3

    const float* Ab = A + ((size_t)sp * ATOMS_PER_S + (size_t)mt * 128) * (size_t)K;
    const uint32_t* Whb = Wh + (size_t)sp * (size_t)(K / 2) * HID + nt * 128;
    const uint32_t* Wlb = Wl + (size_t)sp * (size_t)(K / 2) * HID + nt * 128;

    float acc[4][4][4] = {};

    for (int kt = 0; kt < ksteps; kt++) {
        // ---- global loads (before sync; reads only, no smem hazard) ----
        float4 av[4];
#pragma unroll
        for (int it = 0; it < 4; it++) {
            int idx = tid + it * 256;
            int row = idx >> 3;
            int c4 = idx & 7;
            av[it] = *(const float4*)(Ab + (size_t)row * K + kt * 32 + c4 * 4);
        }
        uint4 bvh[2], bvl[2];
#pragma unroll
        for (int it = 0; it < 2; it++) {
            int idx = tid + it * 256;
            int k2 = idx >> 5;
            int c4 = idx & 31;
            size_t off = (size_t)(kt * 16 + k2) * HID + c4 * 4;
            bvh[it] = *(const uint4*)(Whb + off);
            bvl[it] = *(const uint4*)(Wlb + off);
        }

        __syncthreads();   // previous iteration's MMAs done before overwrite

        // ---- convert + store A tile (packed k-pairs) ----
#pragma unroll
        for (int it = 0; it < 4; it++) {
            int idx = tid + it * 256;
            int row = idx >> 3;
            int c4 = idx & 7;
            uint32_t h01, l01, h23, l23;
            split_pack(av[it].x, av[it].y, h01, l01);
            split_pack(av[it].z, av[it].w, h23, l23);
            *(uint2*)&sAh[row * 20 + c4 * 2] = make_uint2(h01, h23);
            *(uint2*)&sAl[row * 20 + c4 * 2] = make_uint2(l01, l23);
        }
        // ---- store B tile (already packed) ----
#pragma unroll
        for (int it = 0; it < 2; it++) {
            int idx = tid + it * 256;
            int k2 = idx >> 5;
            int c4 = idx & 31;
            *(uint4*)&sBh[k2 * 136 + c4 * 4] = bvh[it];
            *(uint4*)&sBl[k2 * 136 + c4 * 4] = bvl[it];
        }

        __syncthreads();

        // ---- MMA over two k16 chunks ----
#pragma unroll
        for (int kk = 0; kk < 2; kk++) {
            uint32_t bh[4][2], bl[4][2];
#pragma unroll
            for (int j = 0; j < 4; j++) {
                int n = wn * 32 + j * 8 + r;
                int kb = kk * 8 + c;
                bh[j][0] = sBh[kb * 136 + n];
                bh[j][1] = sBh[(kb + 4) * 136 + n];
                bl[j][0] = sBl[kb * 136 + n];
                bl[j][1] = sBl[(kb + 4) * 136 + n];
            }
#pragma unroll
            for (int i = 0; i < 4; i++) {
                int row = wm * 64 + i * 16 + r;
                int ka = kk * 8 + c;
                uint32_t ah0 = sAh[row * 20 + ka];
                uint32_t ah1 = sAh[(row + 8) * 20 + ka];
                uint32_t ah2 = sAh[row * 20 + ka + 4];
                uint32_t ah3 = sAh[(row + 8) * 20 + ka + 4];
                uint32_t al0 = sAl[row * 20 + ka];
                uint32_t al1 = sAl[(row + 8) * 20 + ka];
                uint32_t al2 = sAl[row * 20 + ka + 4];
                uint32_t al3 = sAl[(row + 8) * 20 + ka + 4];
#pragma unroll
                for (int j = 0; j < 4; j++) {
                    mma16816(acc[i][j], ah0, ah1, ah2, ah3, bh[j][0], bh[j][1]);
                    mma16816(acc[i][j], al0, al1, al2, al3, bh[j][0], bh[j][1]);
                    mma16816(acc[i][j], ah0, ah1, ah2, ah3, bl[j][0], bl[j][1]);
                }
            }
        }
    }

    // ---- epilogue: bias + SiLU, fp32 out [N_ATOMS][256] ----
    const float* bb = bias + sp * HID + nt * 128;
#pragma unroll
    for (int i = 0; i < 4; i++) {
        int row = wm * 64 + i * 16 + r;
        size_t atom = (size_t)sp * ATOMS_PER_S + (size_t)mt * 128 + row;
#pragma unroll
        for (int j = 0; j < 4; j++) {
            int cl = wn * 32 + j * 8 + c * 2;
            float b0 = bb[cl], b1 = bb[cl + 1];
            float x0 = silu_f(acc[i][j][0] + b0);
            float x1 = silu_f(acc[i][j][1] + b1);
            float x2 = silu_f(acc[i][j][2] + b0);
            float x3 = silu_f(acc[i][j][3] + b1);
            int colg = nt * 128 + cl;
            *(float2*)&out[atom * HID + colg] = make_float2(x0, x1);
            *(float2*)&out[(atom + 8) * HID + colg] = make_float2(x2, x3);
        }
    }
}

// ---------------- layer 4: per-atom energy (warp per atom) --------------------
__global__ void layer4_kernel(const float* __restrict__ W4,
                              const float* __restrict__ b4) {
    int warp = threadIdx.x >> 5;
    int lane = threadIdx.x & 31;
    int a = blockIdx.x * 8 + warp;
    int s = a >> 13;  // 8192 atoms per species
    const float4* hv = (const float4*)(g_h1 + (size_t)a * HID);
    const float4* wv = (const float4*)(W4 + (size_t)s * HID);
    float sum = 0.f;
#pragma unroll
    for (int t = 0; t < 2; t++) {
        float4 h4 = hv[lane + t * 32];
        float4 w4 = wv[lane + t * 32];
        sum += h4.x * w4.x + h4.y * w4.y + h4.z * w4.z + h4.w * w4.w;
    }
#pragma unroll
    for (int o = 16; o > 0; o >>= 1) sum += __shfl_xor_sync(0xFFFFFFFFu, sum, o);
    if (lane == 0) g_e[a] = sum + b4[s];
}

// ---------------- deterministic segment sum: one block per structure ----------
__global__ void segsum_kernel(const int* __restrict__ sidx,
                              float* __restrict__ out, int n_atoms) {
    __shared__ float red[256];
    int b = blockIdx.x;
    int tid = threadIdx.x;
    float s = 0.f;
    for (int a = tid; a < n_atoms; a += 256) {
        if (sidx[a] == b) s += g_e[a];
    }
    red[tid] = s;
    __syncthreads();
    for (int o = 128; o > 0; o >>= 1) {
        if (tid < o) red[tid] += red[tid + o];
        __syncthreads();
    }
    if (tid == 0) out[b] = red[0];
}

// ---------------- launch ------------------------------------------------------
extern "C" void kernel_launch(void* const* d_in, const int* in_sizes, int n_in,
                              void* d_out, int out_size) {
    const float* features = (const float*)d_in[0];
    const int* sidx = (const int*)d_in[1];
    // n_structures may or may not be materialized as a scalar input.
    int wi = (in_sizes[2] == 1) ? 3 : 2;
    const float* W1 = (const float*)d_in[wi + 0];
    const float* b1 = (const float*)d_in[wi + 1];
    const float* W2 = (const float*)d_in[wi + 2];
    const float* b2 = (const float*)d_in[wi + 3];
    const float* W3 = (const float*)d_in[wi + 4];
    const float* b3 = (const float*)d_in[wi + 5];
    const float* W4 = (const float*)d_in[wi + 6];
    const float* b4 = (const float*)d_in[wi + 7];
    const int n_atoms = in_sizes[1];

    // 1) pre-split weights into packed hi/lo bf16 k-pairs
    const int np1 = N_SPECIES * (NFEAT / 2) * HID;
    const int np23 = N_SPECIES * (HID / 2) * HID;
    conv_w<0><<<(np1 + 255) / 256, 256>>>(W1, np1);
    conv_w<1><<<(np23 + 255) / 256, 256>>>(W2, np23);
    conv_w<2><<<(np23 + 255) / 256, 256>>>(W3, np23);

    // 2) three fused GEMM+bias+SiLU layers
    dim3 grid(ATOMS_PER_S / 128, HID / 128, N_SPECIES);  // (64, 2, 4)
    gemm_silu<0><<<grid, 256>>>(features, b1);
    gemm_silu<1><<<grid, 256>>>(nullptr, b2);
    gemm_silu<2><<<grid, 256>>>(nullptr, b3);

    // 3) per-atom energies
    layer4_kernel<<<n_atoms / 8, 256>>>(W4, b4);

    // 4) deterministic per-structure segment sum
    segsum_kernel<<<out_size, 256>>>(sidx, (float*)d_out, n_atoms);
}

// round 10
// speedup vs baseline: 1.2410x; 1.2410x over previous
#include <cuda_runtime.h>
#include <cuda_bf16.h>
#include <math.h>
#include <stdint.h>
#include <stddef.h>

#define N_SPECIES   4
#define NFEAT       7584
#define HID         256
#define ATOMS_PER_S 8192
#define N_ATOMS_C   32768

// ---------------- scratch (__device__ globals; no allocations) ----------------
__device__ uint32_t g_w1h[N_SPECIES * (NFEAT / 2) * HID];
__device__ uint32_t g_w1l[N_SPECIES * (NFEAT / 2) * HID];
__device__ uint32_t g_w2h[N_SPECIES * (HID / 2) * HID];
__device__ uint32_t g_w2l[N_SPECIES * (HID / 2) * HID];
__device__ uint32_t g_w3h[N_SPECIES * (HID / 2) * HID];
__device__ uint32_t g_w3l[N_SPECIES * (HID / 2) * HID];
__device__ float    g_h1[(size_t)N_ATOMS_C * HID];
__device__ float    g_h2[(size_t)N_ATOMS_C * HID];
__device__ float    g_e[N_ATOMS_C];

// ---------------- smem layout (dynamic), byte offsets --------------------------
// Araw[2] : fp32 A tile 128 rows x 32 f, pitch 36 words (144B)  -> 18432 each
// sAh/sAl[2]: bf16-pair words [row][k2], pitch 20 words          -> 10240 each
// sBh/sBl[2]: bf16-pair words [k2][n], pitch 136 words           ->  8704 each
#define OFF_ARAW 0
#define OFF_AH   36864
#define OFF_AL   57344
#define OFF_BH   77824
#define OFF_BL   95232
#define SMEM_PIPE 112640

// ---------------- PTX helpers --------------------------------------------------
static __device__ __forceinline__ uint32_t smem_u32(const void* p) {
    uint32_t a;
    asm("{ .reg .u64 t; cvta.to.shared.u64 t, %1; cvt.u32.u64 %0, t; }" : "=r"(a) : "l"(p));
    return a;
}

#define CP_ASYNC_CG(dst, src) \
    asm volatile("cp.async.cg.shared.global [%0], [%1], 16;" :: "r"(dst), "l"(src) : "memory")
#define CP_ASYNC_CA(dst, src) \
    asm volatile("cp.async.ca.shared.global [%0], [%1], 16;" :: "r"(dst), "l"(src) : "memory")
#define CP_COMMIT() asm volatile("cp.async.commit_group;" ::: "memory")
#define CP_WAIT0()  asm volatile("cp.async.wait_group 0;" ::: "memory")

#define LDMATRIX_X4(r0, r1, r2, r3, addr) \
    asm volatile("ldmatrix.sync.aligned.m8n8.x4.shared.b16 {%0,%1,%2,%3}, [%4];" \
                 : "=r"(r0), "=r"(r1), "=r"(r2), "=r"(r3) : "r"(addr))

static __device__ __forceinline__ void mma16816(float* d,
                                                uint32_t a0, uint32_t a1, uint32_t a2, uint32_t a3,
                                                uint32_t b0, uint32_t b1) {
    asm volatile(
        "mma.sync.aligned.m16n8k16.row.col.f32.bf16.bf16.f32 "
        "{%0,%1,%2,%3}, {%4,%5,%6,%7}, {%8,%9}, {%0,%1,%2,%3};\n"
        : "+f"(d[0]), "+f"(d[1]), "+f"(d[2]), "+f"(d[3])
        : "r"(a0), "r"(a1), "r"(a2), "r"(a3), "r"(b0), "r"(b1));
}

// ---------------- small math helpers -------------------------------------------
static __device__ __forceinline__ uint32_t pack_bf16(__nv_bfloat16 a, __nv_bfloat16 b) {
    return (uint32_t)__bfloat16_as_ushort(a) | ((uint32_t)__bfloat16_as_ushort(b) << 16);
}
static __device__ __forceinline__ void split_pack(float x0, float x1,
                                                  uint32_t& h, uint32_t& l) {
    __nv_bfloat16 h0 = __float2bfloat16(x0);
    __nv_bfloat16 h1 = __float2bfloat16(x1);
    float r0 = x0 - __bfloat162float(h0);
    float r1 = x1 - __bfloat162float(h1);
    h = pack_bf16(h0, h1);
    l = pack_bf16(__float2bfloat16(r0), __float2bfloat16(r1));
}
static __device__ __forceinline__ float silu_f(float x) {
    return x / (1.0f + expf(-x));
}

// ---------------- weight pre-split: fp32 [S][K][256] -> packed k-pair hi/lo ----
// Word p packs (W[2*k2][n], W[2*k2+1][n]); rp = p>>8 = s*(K/2)+k2, n = p&255.
template <int LAYER>
__global__ void conv_w(const float* __restrict__ W, int npairs) {
    uint32_t* Wh = (LAYER == 0) ? g_w1h : (LAYER == 1) ? g_w2h : g_w3h;
    uint32_t* Wl = (LAYER == 0) ? g_w1l : (LAYER == 1) ? g_w2l : g_w3l;
    int p = blockIdx.x * blockDim.x + threadIdx.x;
    if (p >= npairs) return;
    int n = p & (HID - 1);
    size_t rp = (size_t)(p >> 8);
    size_t src = rp * (2 * HID) + n;
    uint32_t h, l;
    split_pack(W[src], W[src + HID], h, l);
    Wh[p] = h;
    Wl[p] = l;
}

// ---------------- pipelined grouped GEMM + bias + SiLU -------------------------
// out[s*8192+m, n] = silu( A[s*8192+m, :] dot W[s][:, n] + bias[s][n] )
// BM=128, BN=128, BK=32; 256 threads = 8 warps (2x4), warp tile 64x32.
// cp.async double buffer; ldmatrix A fragments; split-bf16 3-product MMA.
template <int LAYER>
__global__ __launch_bounds__(256, 2) void gemm_pipe(
    const float* __restrict__ feat, const float* __restrict__ bias) {

    constexpr int K = (LAYER == 0) ? NFEAT : HID;
    constexpr int ksteps = K >> 5;

    const float* A = (LAYER == 0) ? feat : (LAYER == 1) ? g_h1 : g_h2;
    const uint32_t* Wh = (LAYER == 0) ? g_w1h : (LAYER == 1) ? g_w2h : g_w3h;
    const uint32_t* Wl = (LAYER == 0) ? g_w1l : (LAYER == 1) ? g_w2l : g_w3l;
    float* out = (LAYER == 0) ? g_h1 : (LAYER == 1) ? g_h2 : g_h1;

    extern __shared__ __align__(16) char sm[];
    const uint32_t sbase = smem_u32(sm);

    const int tid  = threadIdx.x;
    const int lane = tid & 31;
    const int warp = tid >> 5;
    const int r = lane >> 2;      // groupID (0..7)
    const int c = lane & 3;       // threadID_in_group (0..3)
    const int wm = warp >> 2;     // 0..1
    const int wn = warp & 3;      // 0..3
    const int mt = blockIdx.x;    // 0..63
    const int nt = blockIdx.y;    // 0..1
    const int sp = blockIdx.z;    // 0..3

    const float* Ab = A + ((size_t)sp * ATOMS_PER_S + (size_t)mt * 128) * (size_t)K;
    const uint32_t* Whb = Wh + (size_t)sp * (size_t)(K / 2) * HID + nt * 128;
    const uint32_t* Wlb = Wl + (size_t)sp * (size_t)(K / 2) * HID + nt * 128;

    // cp.async issue for k-step kt into buffer p
    auto issue = [&](int kt, int p) {
        const uint32_t araw = sbase + OFF_ARAW + p * 18432;
#pragma unroll
        for (int it = 0; it < 4; it++) {
            int ch = tid + it * 256;          // 1024 16B chunks
            int row = ch >> 3, seg = ch & 7;
            const float* src = Ab + (size_t)row * K + kt * 32 + seg * 4;
            CP_ASYNC_CG(araw + row * 144 + seg * 16, src);
        }
        const uint32_t bh = sbase + OFF_BH + p * 8704;
        const uint32_t bl = sbase + OFF_BL + p * 8704;
#pragma unroll
        for (int it = 0; it < 2; it++) {
            int id = tid + it * 256;          // 512 16B chunks
            int k2 = id >> 5, c4 = id & 31;
            size_t off = (size_t)(kt * 16 + k2) * HID + c4 * 4;
            CP_ASYNC_CA(bh + k2 * 544 + c4 * 16, Whb + off);
            CP_ASYNC_CA(bl + k2 * 544 + c4 * 16, Wlb + off);
        }
    };

    float acc[4][4][4] = {};

    // ldmatrix per-lane base (byte offset within sAh/sAl stage):
    // lanes 0-15 -> rows 0-15 (k lo half), lanes 16-31 -> rows 0-15 (k hi half)
    const int rowt  = lane & 15;
    const int khalf = lane >> 4;
    const uint32_t lm_off = (uint32_t)(((wm * 64 + rowt) * 20 + khalf * 4) * 4);

    issue(0, 0);
    CP_COMMIT();

    for (int kt = 0; kt < ksteps; kt++) {
        const int p = kt & 1;
        CP_WAIT0();
        __syncthreads();           // stage p raw data visible; prior reads of p^1 done

        if (kt + 1 < ksteps) issue(kt + 1, p ^ 1);
        CP_COMMIT();

        // ---- convert A: Araw[p] (fp32) -> sAh/sAl[p] (bf16-pair words) ----
        {
            const int row = tid & 127;
            const int half = tid >> 7;        // 0/1: 16-float half of the 32-k row
            const char* ap = sm + OFF_ARAW + p * 18432 + row * 144 + half * 64;
            float4 f0 = *(const float4*)(ap);
            float4 f1 = *(const float4*)(ap + 16);
            float4 f2 = *(const float4*)(ap + 32);
            float4 f3 = *(const float4*)(ap + 48);
            uint32_t h[8], l[8];
            split_pack(f0.x, f0.y, h[0], l[0]);
            split_pack(f0.z, f0.w, h[1], l[1]);
            split_pack(f1.x, f1.y, h[2], l[2]);
            split_pack(f1.z, f1.w, h[3], l[3]);
            split_pack(f2.x, f2.y, h[4], l[4]);
            split_pack(f2.z, f2.w, h[5], l[5]);
            split_pack(f3.x, f3.y, h[6], l[6]);
            split_pack(f3.z, f3.w, h[7], l[7]);
            uint32_t* ah = (uint32_t*)(sm + OFF_AH + p * 10240) + row * 20 + half * 8;
            uint32_t* al = (uint32_t*)(sm + OFF_AL + p * 10240) + row * 20 + half * 8;
            *(uint4*)(ah)     = make_uint4(h[0], h[1], h[2], h[3]);
            *(uint4*)(ah + 4) = make_uint4(h[4], h[5], h[6], h[7]);
            *(uint4*)(al)     = make_uint4(l[0], l[1], l[2], l[3]);
            *(uint4*)(al + 4) = make_uint4(l[4], l[5], l[6], l[7]);
        }
        __syncthreads();

        // ---- MMA phase on stage p ----
        const char* bhp = sm + OFF_BH + p * 8704;
        const char* blp = sm + OFF_BL + p * 8704;
        const uint32_t ah_base = sbase + OFF_AH + p * 10240 + lm_off;
        const uint32_t al_base = sbase + OFF_AL + p * 10240 + lm_off;

#pragma unroll
        for (int kk = 0; kk < 2; kk++) {
            uint32_t bhf[4][2], blf[4][2];
#pragma unroll
            for (int j = 0; j < 4; j++) {
                int n = wn * 32 + j * 8 + r;
                int kb = kk * 8 + c;
                bhf[j][0] = *(const uint32_t*)(bhp + (kb * 136 + n) * 4);
                bhf[j][1] = *(const uint32_t*)(bhp + ((kb + 4) * 136 + n) * 4);
                blf[j][0] = *(const uint32_t*)(blp + (kb * 136 + n) * 4);
                blf[j][1] = *(const uint32_t*)(blp + ((kb + 4) * 136 + n) * 4);
            }
#pragma unroll
            for (int i = 0; i < 4; i++) {
                uint32_t ah0, ah1, ah2, ah3, al0, al1, al2, al3;
                const uint32_t tile = (uint32_t)((i * 320 + kk * 8) * 4);
                LDMATRIX_X4(ah0, ah1, ah2, ah3, ah_base + tile);
                LDMATRIX_X4(al0, al1, al2, al3, al_base + tile);
#pragma unroll
                for (int j = 0; j < 4; j++) {
                    mma16816(acc[i][j], ah0, ah1, ah2, ah3, bhf[j][0], bhf[j][1]);
                    mma16816(acc[i][j], al0, al1, al2, al3, bhf[j][0], bhf[j][1]);
                    mma16816(acc[i][j], ah0, ah1, ah2, ah3, blf[j][0], blf[j][1]);
                }
            }
        }
    }

    // ---- epilogue: bias + SiLU, fp32 out [N_ATOMS][256] ----
    const float* bb = bias + sp * HID + nt * 128;
#pragma unroll
    for (int i = 0; i < 4; i++) {
        int row = wm * 64 + i * 16 + r;
        size_t atom = (size_t)sp * ATOMS_PER_S + (size_t)mt * 128 + row;
#pragma unroll
        for (int j = 0; j < 4; j++) {
            int cl = wn * 32 + j * 8 + c * 2;
            float b0 = bb[cl], b1 = bb[cl + 1];
            float x0 = silu_f(acc[i][j][0] + b0);
            float x1 = silu_f(acc[i][j][1] + b1);
            float x2 = silu_f(acc[i][j][2] + b0);
            float x3 = silu_f(acc[i][j][3] + b1);
            int colg = nt * 128 + cl;
            *(float2*)&out[atom * HID + colg] = make_float2(x0, x1);
            *(float2*)&out[(atom + 8) * HID + colg] = make_float2(x2, x3);
        }
    }
}

// ---------------- layer 4: per-atom energy (warp per atom) --------------------
__global__ void layer4_kernel(const float* __restrict__ W4,
                              const float* __restrict__ b4) {
    int warp = threadIdx.x >> 5;
    int lane = threadIdx.x & 31;
    int a = blockIdx.x * 8 + warp;
    int s = a >> 13;  // 8192 atoms per species
    const float4* hv = (const float4*)(g_h1 + (size_t)a * HID);
    const float4* wv = (const float4*)(W4 + (size_t)s * HID);
    float sum = 0.f;
#pragma unroll
    for (int t = 0; t < 2; t++) {
        float4 h4 = hv[lane + t * 32];
        float4 w4 = wv[lane + t * 32];
        sum += h4.x * w4.x + h4.y * w4.y + h4.z * w4.z + h4.w * w4.w;
    }
#pragma unroll
    for (int o = 16; o > 0; o >>= 1) sum += __shfl_xor_sync(0xFFFFFFFFu, sum, o);
    if (lane == 0) g_e[a] = sum + b4[s];
}

// ---------------- deterministic segment sum: one block per structure ----------
__global__ void segsum_kernel(const int* __restrict__ sidx,
                              float* __restrict__ out, int n_atoms) {
    __shared__ float red[256];
    int b = blockIdx.x;
    int tid = threadIdx.x;
    float s = 0.f;
    for (int a = tid; a < n_atoms; a += 256) {
        if (sidx[a] == b) s += g_e[a];
    }
    red[tid] = s;
    __syncthreads();
    for (int o = 128; o > 0; o >>= 1) {
        if (tid < o) red[tid] += red[tid + o];
        __syncthreads();
    }
    if (tid == 0) out[b] = red[0];
}

// ---------------- launch ------------------------------------------------------
extern "C" void kernel_launch(void* const* d_in, const int* in_sizes, int n_in,
                              void* d_out, int out_size) {
    const float* features = (const float*)d_in[0];
    const int* sidx = (const int*)d_in[1];
    int wi = (in_sizes[2] == 1) ? 3 : 2;
    const float* W1 = (const float*)d_in[wi + 0];
    const float* b1 = (const float*)d_in[wi + 1];
    const float* W2 = (const float*)d_in[wi + 2];
    const float* b2 = (const float*)d_in[wi + 3];
    const float* W3 = (const float*)d_in[wi + 4];
    const float* b3 = (const float*)d_in[wi + 5];
    const float* W4 = (const float*)d_in[wi + 6];
    const float* b4 = (const float*)d_in[wi + 7];
    const int n_atoms = in_sizes[1];

    cudaFuncSetAttribute(gemm_pipe<0>, cudaFuncAttributeMaxDynamicSharedMemorySize, SMEM_PIPE);
    cudaFuncSetAttribute(gemm_pipe<1>, cudaFuncAttributeMaxDynamicSharedMemorySize, SMEM_PIPE);
    cudaFuncSetAttribute(gemm_pipe<2>, cudaFuncAttributeMaxDynamicSharedMemorySize, SMEM_PIPE);

    // 1) pre-split weights into packed hi/lo bf16 k-pairs
    const int np1 = N_SPECIES * (NFEAT / 2) * HID;
    const int np23 = N_SPECIES * (HID / 2) * HID;
    conv_w<0><<<(np1 + 255) / 256, 256>>>(W1, np1);
    conv_w<1><<<(np23 + 255) / 256, 256>>>(W2, np23);
    conv_w<2><<<(np23 + 255) / 256, 256>>>(W3, np23);

    // 2) three pipelined GEMM+bias+SiLU layers
    dim3 grid(ATOMS_PER_S / 128, HID / 128, N_SPECIES);  // (64, 2, 4)
    gemm_pipe<0><<<grid, 256, SMEM_PIPE>>>(features, b1);
    gemm_pipe<1><<<grid, 256, SMEM_PIPE>>>(nullptr, b2);
    gemm_pipe<2><<<grid, 256, SMEM_PIPE>>>(nullptr, b3);

    // 3) per-atom energies
    layer4_kernel<<<n_atoms / 8, 256>>>(W4, b4);

    // 4) deterministic per-structure segment sum
    segsum_kernel<<<out_size, 256>>>(sidx, (float*)d_out, n_atoms);
}

// round 13
// speedup vs baseline: 1.2621x; 1.0171x over previous
#include <cuda_runtime.h>
#include <cuda_bf16.h>
#include <math.h>
#include <stdint.h>
#include <stddef.h>

#define N_SPECIES   4
#define NFEAT       7584
#define HID         256
#define ATOMS_PER_S 8192
#define N_ATOMS_C   32768

// ---------------- scratch (__device__ globals; no allocations) ----------------
// Weights stored fragment-ready: per (s, kt) a 4096-word block (16 k2 x 256 n),
// permuted so each warp's B fragments are contiguous 16B chunks.
__device__ uint32_t g_w1h[N_SPECIES * (NFEAT / 2) * HID];
__device__ uint32_t g_w1l[N_SPECIES * (NFEAT / 2) * HID];
__device__ uint32_t g_w2h[N_SPECIES * (HID / 2) * HID];
__device__ uint32_t g_w2l[N_SPECIES * (HID / 2) * HID];
__device__ uint32_t g_w3h[N_SPECIES * (HID / 2) * HID];
__device__ uint32_t g_w3l[N_SPECIES * (HID / 2) * HID];
__device__ float    g_h1[(size_t)N_ATOMS_C * HID];
__device__ float    g_h2[(size_t)N_ATOMS_C * HID];
__device__ float    g_e[N_ATOMS_C];

// ---------------- smem layout (dynamic), byte offsets --------------------------
// Araw[2] : fp32 A tile 128 rows x 32 f, pitch 36 words (144B)  -> 18432 each
// sAh/sAl[2]: bf16-pair words [row][k2], pitch 20 words          -> 10240 each
// sBh/sBl[2]: fragment-ready B, 16KB flat per stage
#define OFF_ARAW 0
#define OFF_AH   36864
#define OFF_AL   57344
#define OFF_BH   77824
#define OFF_BL   110592
#define SMEM_PIPE 143360

// ---------------- PTX helpers --------------------------------------------------
static __device__ __forceinline__ uint32_t smem_u32(const void* p) {
    uint32_t a;
    asm("{ .reg .u64 t; cvta.to.shared.u64 t, %1; cvt.u32.u64 %0, t; }" : "=r"(a) : "l"(p));
    return a;
}

#define CP_ASYNC_CG(dst, src) \
    asm volatile("cp.async.cg.shared.global [%0], [%1], 16;" :: "r"(dst), "l"(src) : "memory")
#define CP_ASYNC_CA(dst, src) \
    asm volatile("cp.async.ca.shared.global [%0], [%1], 16;" :: "r"(dst), "l"(src) : "memory")
#define CP_COMMIT() asm volatile("cp.async.commit_group;" ::: "memory")
#define CP_WAIT0()  asm volatile("cp.async.wait_group 0;" ::: "memory")

#define LDMATRIX_X4(r0, r1, r2, r3, addr) \
    asm volatile("ldmatrix.sync.aligned.m8n8.x4.shared.b16 {%0,%1,%2,%3}, [%4];" \
                 : "=r"(r0), "=r"(r1), "=r"(r2), "=r"(r3) : "r"(addr))

static __device__ __forceinline__ void mma16816(float* d,
                                                uint32_t a0, uint32_t a1, uint32_t a2, uint32_t a3,
                                                uint32_t b0, uint32_t b1) {
    asm volatile(
        "mma.sync.aligned.m16n8k16.row.col.f32.bf16.bf16.f32 "
        "{%0,%1,%2,%3}, {%4,%5,%6,%7}, {%8,%9}, {%0,%1,%2,%3};\n"
        : "+f"(d[0]), "+f"(d[1]), "+f"(d[2]), "+f"(d[3])
        : "r"(a0), "r"(a1), "r"(a2), "r"(a3), "r"(b0), "r"(b1));
}

// ---------------- small math helpers -------------------------------------------
static __device__ __forceinline__ uint32_t pack_bf16(__nv_bfloat16 a, __nv_bfloat16 b) {
    return (uint32_t)__bfloat16_as_ushort(a) | ((uint32_t)__bfloat16_as_ushort(b) << 16);
}
static __device__ __forceinline__ void split_pack(float x0, float x1,
                                                  uint32_t& h, uint32_t& l) {
    __nv_bfloat16 h0 = __float2bfloat16(x0);
    __nv_bfloat16 h1 = __float2bfloat16(x1);
    float r0 = x0 - __bfloat162float(h0);
    float r1 = x1 - __bfloat162float(h1);
    h = pack_bf16(h0, h1);
    l = pack_bf16(__float2bfloat16(r0), __float2bfloat16(r1));
}
static __device__ __forceinline__ float silu_f(float x) {
    return x / (1.0f + expf(-x));
}

// ---------------- weight pre-split into FRAGMENT-READY layout -------------------
// dst word d decomposes as:
//   d = ((((s*KT + kt)*2 + kk)*4 + wn)*4 + u)*128 + lane*4 + w
// with lane=(r*4+c), j = u*2 + (w>>1), pr = w&1,
//   k2 = kt*16 + kk*8 + c + 4*pr          (k-pair row)
//   n  = wn*64 + j*8 + r                  (output column)
// Value packs (W[2*k2][n], W[2*k2+1][n]) as bf16 hi / lo residual.
template <int LAYER>
__global__ void conv_w(const float* __restrict__ W, int nwords) {
    constexpr int K  = (LAYER == 0) ? NFEAT : HID;
    constexpr int KT = K / 32;
    uint32_t* Wh = (LAYER == 0) ? g_w1h : (LAYER == 1) ? g_w2h : g_w3h;
    uint32_t* Wl = (LAYER == 0) ? g_w1l : (LAYER == 1) ? g_w2l : g_w3l;
    int d = blockIdx.x * blockDim.x + threadIdx.x;
    if (d >= nwords) return;
    int w    = d & 3;
    int lane = (d >> 2) & 31;
    int u    = (d >> 7) & 3;
    int wn   = (d >> 9) & 3;
    int kk   = (d >> 11) & 1;
    int t    = d >> 12;
    int kt   = t % KT;
    int s    = t / KT;
    int r = lane >> 2, c = lane & 3;
    int j = u * 2 + (w >> 1);
    int pr = w & 1;
    int k2 = kt * 16 + kk * 8 + c + 4 * pr;
    int n  = wn * 64 + j * 8 + r;
    size_t src = ((size_t)s * K + 2 * k2) * HID + n;
    uint32_t h, l;
    split_pack(W[src], W[src + HID], h, l);
    Wh[d] = h;
    Wl[d] = l;
}

// ---------------- pipelined grouped GEMM + bias + SiLU -------------------------
// out[s*8192+m, n] = silu( A[s*8192+m, :] dot W[s][:, n] + bias[s][n] )
// BM=128, BN=256, BK=32; 256 threads = 8 warps (2x4), warp tile 64x64.
// cp.async double buffer; ldmatrix A frags; LDS.128 fragment-ready B frags.
template <int LAYER>
__global__ __launch_bounds__(256, 1) void gemm_pipe(
    const float* __restrict__ feat, const float* __restrict__ bias) {

    constexpr int K = (LAYER == 0) ? NFEAT : HID;
    constexpr int KT = K / 32;
    constexpr int ksteps = K >> 5;

    const float* A = (LAYER == 0) ? feat : (LAYER == 1) ? g_h1 : g_h2;
    const uint32_t* Wh = (LAYER == 0) ? g_w1h : (LAYER == 1) ? g_w2h : g_w3h;
    const uint32_t* Wl = (LAYER == 0) ? g_w1l : (LAYER == 1) ? g_w2l : g_w3l;
    float* out = (LAYER == 0) ? g_h1 : (LAYER == 1) ? g_h2 : g_h1;

    extern __shared__ __align__(16) char sm[];
    const uint32_t sbase = smem_u32(sm);

    const int tid  = threadIdx.x;
    const int lane = tid & 31;
    const int warp = tid >> 5;
    const int r = lane >> 2;      // groupID (0..7)
    const int c = lane & 3;       // threadID_in_group (0..3)
    const int wm = warp >> 2;     // 0..1
    const int wn = warp & 3;      // 0..3 (64-wide n tile)
    const int mt = blockIdx.x;    // 0..63
    const int sp = blockIdx.y;    // 0..3

    const float* Ab = A + ((size_t)sp * ATOMS_PER_S + (size_t)mt * 128) * (size_t)K;
    const uint32_t* WhS = Wh + (size_t)sp * KT * 4096;
    const uint32_t* WlS = Wl + (size_t)sp * KT * 4096;

    // cp.async issue for k-step kt into buffer p
    auto issue = [&](int kt, int p) {
        const uint32_t araw = sbase + OFF_ARAW + p * 18432;
#pragma unroll
        for (int it = 0; it < 4; it++) {
            int ch = tid + it * 256;          // 1024 16B chunks
            int row = ch >> 3, seg = ch & 7;
            const float* src = Ab + (size_t)row * K + kt * 32 + seg * 4;
            CP_ASYNC_CG(araw + row * 144 + seg * 16, src);
        }
        const uint32_t bh = sbase + OFF_BH + p * 16384;
        const uint32_t bl = sbase + OFF_BL + p * 16384;
        const uint32_t* sh = WhS + (size_t)kt * 4096;
        const uint32_t* slo = WlS + (size_t)kt * 4096;
#pragma unroll
        for (int it = 0; it < 4; it++) {
            int i = tid + it * 256;           // 1024 16B chunks each
            CP_ASYNC_CA(bh + i * 16, sh + i * 4);
            CP_ASYNC_CA(bl + i * 16, slo + i * 4);
        }
    };

    float acc[4][8][4] = {};

    // ldmatrix per-lane base (byte offset within sAh/sAl stage)
    const int rowt  = lane & 15;
    const int khalf = lane >> 4;
    const uint32_t lm_off = (uint32_t)(((wm * 64 + rowt) * 20 + khalf * 4) * 4);

    issue(0, 0);
    CP_COMMIT();

    for (int kt = 0; kt < ksteps; kt++) {
        const int p = kt & 1;
        CP_WAIT0();
        __syncthreads();           // stage p raw data visible; prior reads of p^1 done

        if (kt + 1 < ksteps) issue(kt + 1, p ^ 1);
        CP_COMMIT();

        // ---- convert A: Araw[p] (fp32) -> sAh/sAl[p] (bf16-pair words) ----
        {
            const int row = tid & 127;
            const int half = tid >> 7;        // 0/1: 16-float half of the 32-k row
            const char* ap = sm + OFF_ARAW + p * 18432 + row * 144 + half * 64;
            float4 f0 = *(const float4*)(ap);
            float4 f1 = *(const float4*)(ap + 16);
            float4 f2 = *(const float4*)(ap + 32);
            float4 f3 = *(const float4*)(ap + 48);
            uint32_t h[8], l[8];
            split_pack(f0.x, f0.y, h[0], l[0]);
            split_pack(f0.z, f0.w, h[1], l[1]);
            split_pack(f1.x, f1.y, h[2], l[2]);
            split_pack(f1.z, f1.w, h[3], l[3]);
            split_pack(f2.x, f2.y, h[4], l[4]);
            split_pack(f2.z, f2.w, h[5], l[5]);
            split_pack(f3.x, f3.y, h[6], l[6]);
            split_pack(f3.z, f3.w, h[7], l[7]);
            uint32_t* ah = (uint32_t*)(sm + OFF_AH + p * 10240) + row * 20 + half * 8;
            uint32_t* al = (uint32_t*)(sm + OFF_AL + p * 10240) + row * 20 + half * 8;
            *(uint4*)(ah)     = make_uint4(h[0], h[1], h[2], h[3]);
            *(uint4*)(ah + 4) = make_uint4(h[4], h[5], h[6], h[7]);
            *(uint4*)(al)     = make_uint4(l[0], l[1], l[2], l[3]);
            *(uint4*)(al + 4) = make_uint4(l[4], l[5], l[6], l[7]);
        }
        __syncthreads();

        // ---- MMA phase on stage p ----
        const uint32_t ah_base = sbase + OFF_AH + p * 10240 + lm_off;
        const uint32_t al_base = sbase + OFF_AL + p * 10240 + lm_off;

#pragma unroll
        for (int kk = 0; kk < 2; kk++) {
            // fragment-ready B: 4 conflict-free LDS.128 each for hi and lo
            const char* bbh = sm + OFF_BH + p * 16384 + ((kk * 4 + wn) * 2048);
            const char* bbl = sm + OFF_BL + p * 16384 + ((kk * 4 + wn) * 2048);
            uint32_t bhf[8][2], blf[8][2];
#pragma unroll
            for (int u = 0; u < 4; u++) {
                uint4 vh = *(const uint4*)(bbh + u * 512 + lane * 16);
                uint4 vl = *(const uint4*)(bbl + u * 512 + lane * 16);
                bhf[2 * u][0] = vh.x; bhf[2 * u][1] = vh.y;
                bhf[2 * u + 1][0] = vh.z; bhf[2 * u + 1][1] = vh.w;
                blf[2 * u][0] = vl.x; blf[2 * u][1] = vl.y;
                blf[2 * u + 1][0] = vl.z; blf[2 * u + 1][1] = vl.w;
            }
#pragma unroll
            for (int i = 0; i < 4; i++) {
                uint32_t ah0, ah1, ah2, ah3, al0, al1, al2, al3;
                const uint32_t tile = (uint32_t)((i * 320 + kk * 8) * 4);
                LDMATRIX_X4(ah0, ah1, ah2, ah3, ah_base + tile);
                LDMATRIX_X4(al0, al1, al2, al3, al_base + tile);
#pragma unroll
                for (int j = 0; j < 8; j++) {
                    mma16816(acc[i][j], ah0, ah1, ah2, ah3, bhf[j][0], bhf[j][1]);
                    mma16816(acc[i][j], al0, al1, al2, al3, bhf[j][0], bhf[j][1]);
                    mma16816(acc[i][j], ah0, ah1, ah2, ah3, blf[j][0], blf[j][1]);
                }
            }
        }
    }

    // ---- epilogue: bias + SiLU, fp32 out [N_ATOMS][256] ----
    const float* bb = bias + sp * HID;
#pragma unroll
    for (int i = 0; i < 4; i++) {
        int row = wm * 64 + i * 16 + r;
        size_t atom = (size_t)sp * ATOMS_PER_S + (size_t)mt * 128 + row;
#pragma unroll
        for (int j = 0; j < 8; j++) {
            int cl = wn * 64 + j * 8 + c * 2;
            float b0 = bb[cl], b1 = bb[cl + 1];
            float x0 = silu_f(acc[i][j][0] + b0);
            float x1 = silu_f(acc[i][j][1] + b1);
            float x2 = silu_f(acc[i][j][2] + b0);
            float x3 = silu_f(acc[i][j][3] + b1);
            *(float2*)&out[atom * HID + cl] = make_float2(x0, x1);
            *(float2*)&out[(atom + 8) * HID + cl] = make_float2(x2, x3);
        }
    }
}

// ---------------- layer 4: per-atom energy (warp per atom) --------------------
__global__ void layer4_kernel(const float* __restrict__ W4,
                              const float* __restrict__ b4) {
    int warp = threadIdx.x >> 5;
    int lane = threadIdx.x & 31;
    int a = blockIdx.x * 8 + warp;
    int s = a >> 13;  // 8192 atoms per species
    const float4* hv = (const float4*)(g_h1 + (size_t)a * HID);
    const float4* wv = (const float4*)(W4 + (size_t)s * HID);
    float sum = 0.f;
#pragma unroll
    for (int t = 0; t < 2; t++) {
        float4 h4 = hv[lane + t * 32];
        float4 w4 = wv[lane + t * 32];
        sum += h4.x * w4.x + h4.y * w4.y + h4.z * w4.z + h4.w * w4.w;
    }
#pragma unroll
    for (int o = 16; o > 0; o >>= 1) sum += __shfl_xor_sync(0xFFFFFFFFu, sum, o);
    if (lane == 0) g_e[a] = sum + b4[s];
}

// ---------------- deterministic segment sum: one block per structure ----------
__global__ void segsum_kernel(const int* __restrict__ sidx,
                              float* __restrict__ out, int n_atoms) {
    __shared__ float red[256];
    int b = blockIdx.x;
    int tid = threadIdx.x;
    float s = 0.f;
    for (int a = tid; a < n_atoms; a += 256) {
        if (sidx[a] == b) s += g_e[a];
    }
    red[tid] = s;
    __syncthreads();
    for (int o = 128; o > 0; o >>= 1) {
        if (tid < o) red[tid] += red[tid + o];
        __syncthreads();
    }
    if (tid == 0) out[b] = red[0];
}

// ---------------- launch ------------------------------------------------------
extern "C" void kernel_launch(void* const* d_in, const int* in_sizes, int n_in,
                              void* d_out, int out_size) {
    const float* features = (const float*)d_in[0];
    const int* sidx = (const int*)d_in[1];
    int wi = (in_sizes[2] == 1) ? 3 : 2;
    const float* W1 = (const float*)d_in[wi + 0];
    const float* b1 = (const float*)d_in[wi + 1];
    const float* W2 = (const float*)d_in[wi + 2];
    const float* b2 = (const float*)d_in[wi + 3];
    const float* W3 = (const float*)d_in[wi + 4];
    const float* b3 = (const float*)d_in[wi + 5];
    const float* W4 = (const float*)d_in[wi + 6];
    const float* b4 = (const float*)d_in[wi + 7];
    const int n_atoms = in_sizes[1];

    cudaFuncSetAttribute(gemm_pipe<0>, cudaFuncAttributeMaxDynamicSharedMemorySize, SMEM_PIPE);
    cudaFuncSetAttribute(gemm_pipe<1>, cudaFuncAttributeMaxDynamicSharedMemorySize, SMEM_PIPE);
    cudaFuncSetAttribute(gemm_pipe<2>, cudaFuncAttributeMaxDynamicSharedMemorySize, SMEM_PIPE);

    // 1) pre-split weights into fragment-ready hi/lo layout
    const int np1 = N_SPECIES * (NFEAT / 2) * HID;
    const int np23 = N_SPECIES * (HID / 2) * HID;
    conv_w<0><<<(np1 + 255) / 256, 256>>>(W1, np1);
    conv_w<1><<<(np23 + 255) / 256, 256>>>(W2, np23);
    conv_w<2><<<(np23 + 255) / 256, 256>>>(W3, np23);

    // 2) three pipelined GEMM+bias+SiLU layers (128x256 tile per CTA)
    dim3 grid(ATOMS_PER_S / 128, N_SPECIES);   // (64, 4)
    gemm_pipe<0><<<grid, 256, SMEM_PIPE>>>(features, b1);
    gemm_pipe<1><<<grid, 256, SMEM_PIPE>>>(nullptr, b2);
    gemm_pipe<2><<<grid, 256, SMEM_PIPE>>>(nullptr, b3);

    // 3) per-atom energies
    layer4_kernel<<<n_atoms / 8, 256>>>(W4, b4);

    // 4) deterministic per-structure segment sum
    segsum_kernel<<<out_size, 256>>>(sidx, (float*)d_out, n_atoms);
}

// round 16
// speedup vs baseline: 1.2840x; 1.0174x over previous
#include <cuda_runtime.h>
#include <cuda_bf16.h>
#include <math.h>
#include <stdint.h>
#include <stddef.h>

#define N_SPECIES   4
#define NFEAT       7584
#define HID         256
#define ATOMS_PER_S 8192
#define N_ATOMS_C   32768

// ---------------- scratch (__device__ globals; no allocations) ----------------
// Weights fragment-ready: per (s,kt) a 4096-word block; within it, per
// (nt,kk,wn,u) a 128-word chunk holding one warp's B fragment quad.
__device__ uint32_t g_w1h[N_SPECIES * (NFEAT / 2) * HID];
__device__ uint32_t g_w1l[N_SPECIES * (NFEAT / 2) * HID];
__device__ uint32_t g_w2h[N_SPECIES * (HID / 2) * HID];
__device__ uint32_t g_w2l[N_SPECIES * (HID / 2) * HID];
__device__ uint32_t g_w3h[N_SPECIES * (HID / 2) * HID];
__device__ uint32_t g_w3l[N_SPECIES * (HID / 2) * HID];
__device__ float    g_h1[(size_t)N_ATOMS_C * HID];
__device__ float    g_h2[(size_t)N_ATOMS_C * HID];
__device__ float    g_e[N_ATOMS_C];

// ---------------- smem layout (dynamic), byte offsets --------------------------
// Araw[2] : fp32 A tile 128 rows x 32 f, pitch 36 words (144B)  -> 18432 each
// sAh/sAl[2]: bf16-pair words [row][k2], pitch 20 words          -> 10240 each
// sBh/sBl[2]: fragment-ready B, 8KB flat per stage
#define OFF_ARAW 0
#define OFF_AH   36864
#define OFF_AL   57344
#define OFF_BH   77824
#define OFF_BL   94208
#define SMEM_PIPE 110592

// ---------------- PTX helpers --------------------------------------------------
static __device__ __forceinline__ uint32_t smem_u32(const void* p) {
    uint32_t a;
    asm("{ .reg .u64 t; cvta.to.shared.u64 t, %1; cvt.u32.u64 %0, t; }" : "=r"(a) : "l"(p));
    return a;
}

#define CP_ASYNC_CG(dst, src) \
    asm volatile("cp.async.cg.shared.global [%0], [%1], 16;" :: "r"(dst), "l"(src) : "memory")
#define CP_ASYNC_CA(dst, src) \
    asm volatile("cp.async.ca.shared.global [%0], [%1], 16;" :: "r"(dst), "l"(src) : "memory")
#define CP_COMMIT() asm volatile("cp.async.commit_group;" ::: "memory")
#define CP_WAIT0()  asm volatile("cp.async.wait_group 0;" ::: "memory")

#define LDMATRIX_X4(r0, r1, r2, r3, addr) \
    asm volatile("ldmatrix.sync.aligned.m8n8.x4.shared.b16 {%0,%1,%2,%3}, [%4];" \
                 : "=r"(r0), "=r"(r1), "=r"(r2), "=r"(r3) : "r"(addr))

static __device__ __forceinline__ void mma16816(float* d,
                                                uint32_t a0, uint32_t a1, uint32_t a2, uint32_t a3,
                                                uint32_t b0, uint32_t b1) {
    asm volatile(
        "mma.sync.aligned.m16n8k16.row.col.f32.bf16.bf16.f32 "
        "{%0,%1,%2,%3}, {%4,%5,%6,%7}, {%8,%9}, {%0,%1,%2,%3};\n"
        : "+f"(d[0]), "+f"(d[1]), "+f"(d[2]), "+f"(d[3])
        : "r"(a0), "r"(a1), "r"(a2), "r"(a3), "r"(b0), "r"(b1));
}

// ---------------- small math helpers -------------------------------------------
static __device__ __forceinline__ uint32_t pack_bf16(__nv_bfloat16 a, __nv_bfloat16 b) {
    return (uint32_t)__bfloat16_as_ushort(a) | ((uint32_t)__bfloat16_as_ushort(b) << 16);
}
static __device__ __forceinline__ void split_pack(float x0, float x1,
                                                  uint32_t& h, uint32_t& l) {
    __nv_bfloat16 h0 = __float2bfloat16(x0);
    __nv_bfloat16 h1 = __float2bfloat16(x1);
    float r0 = x0 - __bfloat162float(h0);
    float r1 = x1 - __bfloat162float(h1);
    h = pack_bf16(h0, h1);
    l = pack_bf16(__float2bfloat16(r0), __float2bfloat16(r1));
}
static __device__ __forceinline__ float silu_f(float x) {
    return x / (1.0f + expf(-x));
}

// ---------------- weight pre-split into FRAGMENT-READY layout -------------------
// dst word d = (((((s*KT + kt)*2 + nt)*2 + kk)*4 + wn)*2 + u)*128 + lane*4 + w
// with lane = r*4 + c, j = u*2 + (w>>1), pr = w&1:
//   k2 = kt*16 + kk*8 + c + 4*pr
//   n  = nt*128 + wn*32 + j*8 + r
// Value packs (W[2*k2][n], W[2*k2+1][n]) as bf16 hi / lo residual.
template <int LAYER>
__global__ void conv_w(const float* __restrict__ W, int nwords) {
    constexpr int K  = (LAYER == 0) ? NFEAT : HID;
    constexpr int KT = K / 32;
    uint32_t* Wh = (LAYER == 0) ? g_w1h : (LAYER == 1) ? g_w2h : g_w3h;
    uint32_t* Wl = (LAYER == 0) ? g_w1l : (LAYER == 1) ? g_w2l : g_w3l;
    int d = blockIdx.x * blockDim.x + threadIdx.x;
    if (d >= nwords) return;
    int w    = d & 3;
    int lane = (d >> 2) & 31;
    int u    = (d >> 7) & 1;
    int wn   = (d >> 8) & 3;
    int kk   = (d >> 10) & 1;
    int nt   = (d >> 11) & 1;
    int t    = d >> 12;
    int kt   = t % KT;
    int s    = t / KT;
    int r = lane >> 2, c = lane & 3;
    int j = u * 2 + (w >> 1);
    int pr = w & 1;
    int k2 = kt * 16 + kk * 8 + c + 4 * pr;
    int n  = nt * 128 + wn * 32 + j * 8 + r;
    size_t src = ((size_t)s * K + 2 * k2) * HID + n;
    uint32_t h, l;
    split_pack(W[src], W[src + HID], h, l);
    Wh[d] = h;
    Wl[d] = l;
}

// ---------------- pipelined grouped GEMM + bias + SiLU -------------------------
// BM=128, BN=128, BK=32; 256 threads = 8 warps (2x4), warp tile 64x32.
// 2 CTAs/SM hide the convert phase; fragment-ready B cuts LSU traffic.
template <int LAYER>
__global__ __launch_bounds__(256, 2) void gemm_pipe(
    const float* __restrict__ feat, const float* __restrict__ bias) {

    constexpr int K = (LAYER == 0) ? NFEAT : HID;
    constexpr int KT = K / 32;
    constexpr int ksteps = K >> 5;

    const float* A = (LAYER == 0) ? feat : (LAYER == 1) ? g_h1 : g_h2;
    const uint32_t* Wh = (LAYER == 0) ? g_w1h : (LAYER == 1) ? g_w2h : g_w3h;
    const uint32_t* Wl = (LAYER == 0) ? g_w1l : (LAYER == 1) ? g_w2l : g_w3l;
    float* out = (LAYER == 0) ? g_h1 : (LAYER == 1) ? g_h2 : g_h1;

    extern __shared__ __align__(16) char sm[];
    const uint32_t sbase = smem_u32(sm);

    const int tid  = threadIdx.x;
    const int lane = tid & 31;
    const int warp = tid >> 5;
    const int r = lane >> 2;      // groupID (0..7)
    const int c = lane & 3;       // threadID_in_group (0..3)
    const int wm = warp >> 2;     // 0..1
    const int wn = warp & 3;      // 0..3
    const int mt = blockIdx.x;    // 0..63
    const int nt = blockIdx.y;    // 0..1
    const int sp = blockIdx.z;    // 0..3

    const float* Ab = A + ((size_t)sp * ATOMS_PER_S + (size_t)mt * 128) * (size_t)K;
    const uint32_t* WhS = Wh + (size_t)sp * KT * 4096;
    const uint32_t* WlS = Wl + (size_t)sp * KT * 4096;

    // cp.async issue for k-step kt into buffer p
    auto issue = [&](int kt, int p) {
        const uint32_t araw = sbase + OFF_ARAW + p * 18432;
#pragma unroll
        for (int it = 0; it < 4; it++) {
            int ch = tid + it * 256;          // 1024 16B chunks
            int row = ch >> 3, seg = ch & 7;
            const float* src = Ab + (size_t)row * K + kt * 32 + seg * 4;
            CP_ASYNC_CG(araw + row * 144 + seg * 16, src);
        }
        const uint32_t bh = sbase + OFF_BH + p * 8192;
        const uint32_t bl = sbase + OFF_BL + p * 8192;
        const uint32_t* sh  = WhS + ((size_t)kt * 2 + nt) * 2048;
        const uint32_t* slo = WlS + ((size_t)kt * 2 + nt) * 2048;
#pragma unroll
        for (int it = 0; it < 2; it++) {
            int i = tid + it * 256;           // 512 16B chunks each
            CP_ASYNC_CA(bh + i * 16, sh + i * 4);
            CP_ASYNC_CA(bl + i * 16, slo + i * 4);
        }
    };

    float acc[4][4][4] = {};

    // ldmatrix per-lane base (byte offset within sAh/sAl stage)
    const int rowt  = lane & 15;
    const int khalf = lane >> 4;
    const uint32_t lm_off = (uint32_t)(((wm * 64 + rowt) * 20 + khalf * 4) * 4);

    issue(0, 0);
    CP_COMMIT();

    for (int kt = 0; kt < ksteps; kt++) {
        const int p = kt & 1;
        CP_WAIT0();
        __syncthreads();           // stage p raw data visible; prior reads of p^1 done

        if (kt + 1 < ksteps) issue(kt + 1, p ^ 1);
        CP_COMMIT();

        // ---- convert A: Araw[p] (fp32) -> sAh/sAl[p] (bf16-pair words) ----
        {
            const int row = tid & 127;
            const int half = tid >> 7;        // 0/1: 16-float half of the 32-k row
            const char* ap = sm + OFF_ARAW + p * 18432 + row * 144 + half * 64;
            float4 f0 = *(const float4*)(ap);
            float4 f1 = *(const float4*)(ap + 16);
            float4 f2 = *(const float4*)(ap + 32);
            float4 f3 = *(const float4*)(ap + 48);
            uint32_t h[8], l[8];
            split_pack(f0.x, f0.y, h[0], l[0]);
            split_pack(f0.z, f0.w, h[1], l[1]);
            split_pack(f1.x, f1.y, h[2], l[2]);
            split_pack(f1.z, f1.w, h[3], l[3]);
            split_pack(f2.x, f2.y, h[4], l[4]);
            split_pack(f2.z, f2.w, h[5], l[5]);
            split_pack(f3.x, f3.y, h[6], l[6]);
            split_pack(f3.z, f3.w, h[7], l[7]);
            uint32_t* ah = (uint32_t*)(sm + OFF_AH + p * 10240) + row * 20 + half * 8;
            uint32_t* al = (uint32_t*)(sm + OFF_AL + p * 10240) + row * 20 + half * 8;
            *(uint4*)(ah)     = make_uint4(h[0], h[1], h[2], h[3]);
            *(uint4*)(ah + 4) = make_uint4(h[4], h[5], h[6], h[7]);
            *(uint4*)(al)     = make_uint4(l[0], l[1], l[2], l[3]);
            *(uint4*)(al + 4) = make_uint4(l[4], l[5], l[6], l[7]);
        }
        __syncthreads();

        // ---- MMA phase on stage p ----
        const uint32_t ah_base = sbase + OFF_AH + p * 10240 + lm_off;
        const uint32_t al_base = sbase + OFF_AL + p * 10240 + lm_off;

#pragma unroll
        for (int kk = 0; kk < 2; kk++) {
            // fragment-ready B: 2+2 conflict-free LDS.128
            const char* bbh = sm + OFF_BH + p * 8192 + ((kk * 4 + wn) * 1024);
            const char* bbl = sm + OFF_BL + p * 8192 + ((kk * 4 + wn) * 1024);
            uint32_t bhf[4][2], blf[4][2];
#pragma unroll
            for (int u = 0; u < 2; u++) {
                uint4 vh = *(const uint4*)(bbh + u * 512 + lane * 16);
                uint4 vl = *(const uint4*)(bbl + u * 512 + lane * 16);
                bhf[2 * u][0] = vh.x; bhf[2 * u][1] = vh.y;
                bhf[2 * u + 1][0] = vh.z; bhf[2 * u + 1][1] = vh.w;
                blf[2 * u][0] = vl.x; blf[2 * u][1] = vl.y;
                blf[2 * u + 1][0] = vl.z; blf[2 * u + 1][1] = vl.w;
            }
#pragma unroll
            for (int i = 0; i < 4; i++) {
                uint32_t ah0, ah1, ah2, ah3, al0, al1, al2, al3;
                const uint32_t tile = (uint32_t)((i * 320 + kk * 8) * 4);
                LDMATRIX_X4(ah0, ah1, ah2, ah3, ah_base + tile);
                LDMATRIX_X4(al0, al1, al2, al3, al_base + tile);
#pragma unroll
                for (int j = 0; j < 4; j++) {
                    mma16816(acc[i][j], ah0, ah1, ah2, ah3, bhf[j][0], bhf[j][1]);
                    mma16816(acc[i][j], al0, al1, al2, al3, bhf[j][0], bhf[j][1]);
                    mma16816(acc[i][j], ah0, ah1, ah2, ah3, blf[j][0], blf[j][1]);
                }
            }
        }
    }

    // ---- epilogue: bias + SiLU, fp32 out [N_ATOMS][256] ----
    const float* bb = bias + sp * HID + nt * 128;
#pragma unroll
    for (int i = 0; i < 4; i++) {
        int row = wm * 64 + i * 16 + r;
        size_t atom = (size_t)sp * ATOMS_PER_S + (size_t)mt * 128 + row;
#pragma unroll
        for (int j = 0; j < 4; j++) {
            int cl = wn * 32 + j * 8 + c * 2;
            float b0 = bb[cl], b1 = bb[cl + 1];
            float x0 = silu_f(acc[i][j][0] + b0);
            float x1 = silu_f(acc[i][j][1] + b1);
            float x2 = silu_f(acc[i][j][2] + b0);
            float x3 = silu_f(acc[i][j][3] + b1);
            int colg = nt * 128 + cl;
            *(float2*)&out[atom * HID + colg] = make_float2(x0, x1);
            *(float2*)&out[(atom + 8) * HID + colg] = make_float2(x2, x3);
        }
    }
}

// ---------------- layer 4: per-atom energy (warp per atom) --------------------
__global__ void layer4_kernel(const float* __restrict__ W4,
                              const float* __restrict__ b4) {
    int warp = threadIdx.x >> 5;
    int lane = threadIdx.x & 31;
    int a = blockIdx.x * 8 + warp;
    int s = a >> 13;  // 8192 atoms per species
    const float4* hv = (const float4*)(g_h1 + (size_t)a * HID);
    const float4* wv = (const float4*)(W4 + (size_t)s * HID);
    float sum = 0.f;
#pragma unroll
    for (int t = 0; t < 2; t++) {
        float4 h4 = hv[lane + t * 32];
        float4 w4 = wv[lane + t * 32];
        sum += h4.x * w4.x + h4.y * w4.y + h4.z * w4.z + h4.w * w4.w;
    }
#pragma unroll
    for (int o = 16; o > 0; o >>= 1) sum += __shfl_xor_sync(0xFFFFFFFFu, sum, o);
    if (lane == 0) g_e[a] = sum + b4[s];
}

// ---------------- deterministic segment sum: one block per structure ----------
__global__ void segsum_kernel(const int* __restrict__ sidx,
                              float* __restrict__ out, int n_atoms) {
    __shared__ float red[256];
    int b = blockIdx.x;
    int tid = threadIdx.x;
    float s = 0.f;
    for (int a = tid; a < n_atoms; a += 256) {
        if (sidx[a] == b) s += g_e[a];
    }
    red[tid] = s;
    __syncthreads();
    for (int o = 128; o > 0; o >>= 1) {
        if (tid < o) red[tid] += red[tid + o];
        __syncthreads();
    }
    if (tid == 0) out[b] = red[0];
}

// ---------------- launch ------------------------------------------------------
extern "C" void kernel_launch(void* const* d_in, const int* in_sizes, int n_in,
                              void* d_out, int out_size) {
    const float* features = (const float*)d_in[0];
    const int* sidx = (const int*)d_in[1];
    int wi = (in_sizes[2] == 1) ? 3 : 2;
    const float* W1 = (const float*)d_in[wi + 0];
    const float* b1 = (const float*)d_in[wi + 1];
    const float* W2 = (const float*)d_in[wi + 2];
    const float* b2 = (const float*)d_in[wi + 3];
    const float* W3 = (const float*)d_in[wi + 4];
    const float* b3 = (const float*)d_in[wi + 5];
    const float* W4 = (const float*)d_in[wi + 6];
    const float* b4 = (const float*)d_in[wi + 7];
    const int n_atoms = in_sizes[1];

    cudaFuncSetAttribute(gemm_pipe<0>, cudaFuncAttributeMaxDynamicSharedMemorySize, SMEM_PIPE);
    cudaFuncSetAttribute(gemm_pipe<1>, cudaFuncAttributeMaxDynamicSharedMemorySize, SMEM_PIPE);
    cudaFuncSetAttribute(gemm_pipe<2>, cudaFuncAttributeMaxDynamicSharedMemorySize, SMEM_PIPE);

    // 1) pre-split weights into fragment-ready hi/lo layout
    const int np1 = N_SPECIES * (NFEAT / 2) * HID;
    const int np23 = N_SPECIES * (HID / 2) * HID;
    conv_w<0><<<(np1 + 255) / 256, 256>>>(W1, np1);
    conv_w<1><<<(np23 + 255) / 256, 256>>>(W2, np23);
    conv_w<2><<<(np23 + 255) / 256, 256>>>(W3, np23);

    // 2) three pipelined GEMM+bias+SiLU layers
    dim3 grid(ATOMS_PER_S / 128, HID / 128, N_SPECIES);  // (64, 2, 4)
    gemm_pipe<0><<<grid, 256, SMEM_PIPE>>>(features, b1);
    gemm_pipe<1><<<grid, 256, SMEM_PIPE>>>(nullptr, b2);
    gemm_pipe<2><<<grid, 256, SMEM_PIPE>>>(nullptr, b3);

    // 3) per-atom energies
    layer4_kernel<<<n_atoms / 8, 256>>>(W4, b4);

    // 4) deterministic per-structure segment sum
    segsum_kernel<<<out_size, 256>>>(sidx, (float*)d_out, n_atoms);
}